// round 14
// baseline (speedup 1.0000x reference)
#include <cuda_runtime.h>
#include <cuda_fp16.h>
#include <cuda_bf16.h>
#include <math.h>
#include <float.h>
#include <stdint.h>

#define T_TOT   16384
#define IN_DIM  3072
#define V_DIM   768
#define HEADS   4
#define KNN     32
#define N_KEYS  128
#define NCAT    1792            // 768 (dense) + 1024 (scores)
#define BM      128
#define BN      128
#define BK      64
#define STAGES  3
#define NCHUNK  48              // IN_DIM / BK
#define STAGE_BYTES (BM * BK * 2 + BN * BK * 2)   // 32768
#define SMEM_TOTAL  (STAGES * STAGE_BYTES)        // 98304
#define PREP_SMEM   (128 * 129 * 4 + 128 * 128 * 4)  // 131584
#define MCHUNKS 4
#define BM_PER_CHUNK (T_TOT / BM / MCHUNKS)       // 32
#define TOK_PER_CHUNK (T_TOT / MCHUNKS)           // 4096

// ---------------- scratch (device globals; no allocation allowed) ----------
__device__ __align__(256) __half g_Ah[(size_t)T_TOT * IN_DIM];
__device__ __align__(256) __half g_Bh[(size_t)NCAT * IN_DIM];
__device__ __align__(256) float g_bias[NCAT];
__device__ __align__(256) float g_C[(size_t)T_TOT * NCAT];
__device__ __align__(256) __nv_bfloat16 g_vb[(size_t)(N_KEYS * N_KEYS) * V_DIM];

// pruned product-key candidate table: (i<<5)|j for all (i+1)*(j+1) <= 32
__constant__ unsigned short c_tab[128] = {
    0,1,2,3,4,5,6,7,8,9,10,11,12,13,14,15,
    16,17,18,19,20,21,22,23,24,25,26,27,28,29,30,31,
    32,33,34,35,36,37,38,39,40,41,42,43,44,45,46,47,
    64,65,66,67,68,69,70,71,72,73,
    96,97,98,99,100,101,102,103,
    128,129,130,131,132,133,
    160,161,162,163,164,
    192,193,194,195,
    224,225,226,227,
    256,257,258,
    288,289,290,
    320,321, 352,353, 384,385, 416,417, 448,449, 480,481,
    512,544,576,608,640,672,704,736,768,800,832,864,896,928,960,992,
    0,0,0,0,0,0,0,0,0
};

// ---------------- PTX helpers ----------------------------------------------
__device__ __forceinline__ uint32_t smem_u32(const void* p) {
    uint32_t a;
    asm("{ .reg .u64 t; cvta.to.shared.u64 t, %1; cvt.u32.u64 %0, t; }" : "=r"(a) : "l"(p));
    return a;
}
#define SW128(off) ((off) ^ (((off) >> 3) & 0x70))

__device__ __forceinline__ void cp_async16(uint32_t dst, const void* src) {
    asm volatile("cp.async.cg.shared.global [%0], [%1], 16;" :: "r"(dst), "l"(src));
}
#define CP_COMMIT() asm volatile("cp.async.commit_group;" ::: "memory")
#define CP_WAIT1()  asm volatile("cp.async.wait_group 1;" ::: "memory")

#define LDSM4(r0, r1, r2, r3, addr) \
    asm volatile("ldmatrix.sync.aligned.m8n8.x4.shared.b16 {%0,%1,%2,%3}, [%4];" \
                 : "=r"(r0), "=r"(r1), "=r"(r2), "=r"(r3) : "r"(addr))

#define MMA16816(d, a0, a1, a2, a3, b0, b1) \
    asm volatile("mma.sync.aligned.m16n8k16.row.col.f32.f16.f16.f32 " \
                 "{%0,%1,%2,%3}, {%4,%5,%6,%7}, {%8,%9}, {%0,%1,%2,%3};" \
                 : "+f"((d)[0]), "+f"((d)[1]), "+f"((d)[2]), "+f"((d)[3]) \
                 : "r"(a0), "r"(a1), "r"(a2), "r"(a3), "r"(b0), "r"(b1))

// ---------------- prep: A -> fp16 + transpose W_dense -----------------------
__global__ __launch_bounds__(256) void split_trans(
    const float* __restrict__ X, const float* __restrict__ W)
{
    __shared__ float tile[32][33];
    const int b = blockIdx.x, t = threadIdx.x;
    if (b < 49152) {
        size_t i = (size_t)b * 256 + t;          // one float4
        float4 v = ((const float4*)X)[i];
        ushort4 h;
        h.x = __half_as_ushort(__float2half_rn(v.x));
        h.y = __half_as_ushort(__float2half_rn(v.y));
        h.z = __half_as_ushort(__float2half_rn(v.z));
        h.w = __half_as_ushort(__float2half_rn(v.w));
        ((ushort4*)g_Ah)[i] = h;
    } else {
        const int b2 = b - 49152;
        const int n0 = (b2 % 24) * 32, k0 = (b2 / 24) * 32;
        const int tx = t & 31, ty = t >> 5;
#pragma unroll
        for (int j = 0; j < 32; j += 8)
            tile[ty + j][tx] = W[(size_t)(k0 + ty + j) * V_DIM + n0 + tx];
        __syncthreads();
#pragma unroll
        for (int j = 0; j < 32; j += 8) {
            int n = n0 + ty + j, k = k0 + tx;
            g_Bh[(size_t)n * IN_DIM + k] = __float2half_rn(tile[tx][ty + j]);
        }
    }
}

// merged: W_keff = Wq x keys^T (rows 768..1791 of g_Bh), score bias, dense bias
__global__ __launch_bounds__(256) void prep_misc(
    const float* __restrict__ Wq, const float* __restrict__ keys,
    const float* __restrict__ bd, const float* __restrict__ bq)
{
    extern __shared__ float sm[];
    float (*Ws)[129] = (float(*)[129])sm;                 // [kloc][d]
    float (*Ks)[128] = (float(*)[128])(sm + 128 * 129);   // [n][d]
    const int b = blockIdx.x, t = threadIdx.x;

    if (b < 192) {
        const int hs = b & 7, kt = b >> 3;
        for (int i = t; i < 128 * 128; i += 256) {
            int r = i >> 7, d = i & 127;
            Ws[r][d] = Wq[(size_t)(kt * 128 + r) * 1024 + hs * 128 + d];
            Ks[r][d] = keys[(size_t)(hs * 128 + r) * 128 + d];
        }
        __syncthreads();
        const int kloc = t & 127, nh = t >> 7;
        for (int no = 0; no < 64; no++) {
            int n = nh * 64 + no;
            float acc = 0.f;
#pragma unroll 8
            for (int d = 0; d < 128; d++) acc += Ws[kloc][d] * Ks[n][d];
            g_Bh[(size_t)(V_DIM + hs * 128 + n) * IN_DIM + kt * 128 + kloc] =
                __float2half_rn(acc);
        }
    } else if (b < 196) {
        int np = (b - 192) * 256 + t;     // 0..1023
        int hs = np >> 7, n = np & 127;
        float acc = 0.f;
        for (int d = 0; d < 128; d++)
            acc += bq[hs * 128 + d] * keys[(size_t)(hs * 128 + n) * 128 + d];
        g_bias[V_DIM + np] = acc;
    } else {
        for (int i = t; i < V_DIM; i += 256) g_bias[i] = bd[i];
    }
}

// ---------------- values table -> bf16 --------------------------------------
__global__ __launch_bounds__(256) void cvt_values(const float* __restrict__ v)
{
    size_t i = (size_t)blockIdx.x * 256 + threadIdx.x;   // one float4
    float4 x = ((const float4*)v)[i];
    ushort4 o;
    o.x = __bfloat16_as_ushort(__float2bfloat16(x.x));
    o.y = __bfloat16_as_ushort(__float2bfloat16(x.y));
    o.z = __bfloat16_as_ushort(__float2bfloat16(x.z));
    o.w = __bfloat16_as_ushort(__float2bfloat16(x.w));
    ((ushort4*)g_vb)[i] = o;
}

// ---------------- HMMA GEMM: 128x128 CTA tile, 64x64 warp tile, 2 CTA/SM ---
__device__ __forceinline__ void load_chunk(
    int chunk, int s, int tid, int bm, int bn, uint32_t sb)
{
    int k0 = chunk * BK;
    const __half* Ag = g_Ah + (size_t)(bm * BM) * IN_DIM + k0;
    const __half* Bg = g_Bh + (size_t)(bn * BN) * IN_DIM + k0;
    uint32_t sA = sb + s * STAGE_BYTES;
    uint32_t sB = sA + BM * BK * 2;
#pragma unroll
    for (int it = 0; it < 8; it++) {      // A: 1024 x 16B over 128 threads
        int u = tid + it * 128;
        int r = u >> 3, ch = u & 7;
        cp_async16(sA + SW128(r * 128 + ch * 16), Ag + (size_t)r * IN_DIM + ch * 8);
    }
#pragma unroll
    for (int it = 0; it < 8; it++) {      // B: 1024 x 16B
        int u = tid + it * 128;
        int r = u >> 3, ch = u & 7;
        cp_async16(sB + SW128(r * 128 + ch * 16), Bg + (size_t)r * IN_DIM + ch * 8);
    }
}

__global__ __launch_bounds__(128, 2) void gemm_hmma(float* __restrict__ C, int bm0)
{
    extern __shared__ char smem[];
    uint32_t sb = smem_u32(smem);
    const int tid = threadIdx.x, wid = tid >> 5, lane = tid & 31;
    const int bn = blockIdx.x, bm = bm0 + blockIdx.y;
    const int wm = wid & 1;          // M half: rows wm*64
    const int wn = wid >> 1;         // N half: cols wn*64

    float acc[4][8][4];
#pragma unroll
    for (int a = 0; a < 4; a++)
#pragma unroll
        for (int b = 0; b < 8; b++)
#pragma unroll
            for (int c = 0; c < 4; c++) acc[a][b][c] = 0.f;

    const int sub = lane >> 3, lr = lane & 7;
    const int arow0 = wm * 64 + ((sub & 1) << 3) + lr;   // + mi*16
    const int akc = sub >> 1;
    const int brow0 = wn * 64 + ((sub >> 1) << 3) + lr;  // + nj*16
    const int bkc = sub & 1;

#pragma unroll
    for (int s = 0; s < STAGES - 1; s++) {
        load_chunk(s, s, tid, bm, bn, sb);
        CP_COMMIT();
    }

    int s = 0;
    for (int i = 0; i < NCHUNK; i++) {
        CP_WAIT1();
        __syncthreads();
        const int nc = i + STAGES - 1;
        if (nc < NCHUNK) {
            int sp = s + STAGES - 1; if (sp >= STAGES) sp -= STAGES;
            load_chunk(nc, sp, tid, bm, bn, sb);
        }
        CP_COMMIT();

        const uint32_t sA = sb + s * STAGE_BYTES;
        const uint32_t sB = sA + BM * BK * 2;
#pragma unroll
        for (int ks = 0; ks < 4; ks++) {
            uint32_t a[4][4];
#pragma unroll
            for (int mi = 0; mi < 4; mi++) {
                int row = arow0 + mi * 16;
                uint32_t ad = sA + row * 128 + (((2 * ks + akc) ^ (row & 7)) << 4);
                LDSM4(a[mi][0], a[mi][1], a[mi][2], a[mi][3], ad);
            }
            uint32_t b[4][4];
#pragma unroll
            for (int nj = 0; nj < 4; nj++) {
                int row = brow0 + nj * 16;
                uint32_t bd = sB + row * 128 + (((2 * ks + bkc) ^ (row & 7)) << 4);
                LDSM4(b[nj][0], b[nj][1], b[nj][2], b[nj][3], bd);
            }
#pragma unroll
            for (int mi = 0; mi < 4; mi++)
#pragma unroll
                for (int nj = 0; nj < 4; nj++) {
                    MMA16816(acc[mi][2 * nj],     a[mi][0], a[mi][1], a[mi][2], a[mi][3],
                             b[nj][0], b[nj][1]);
                    MMA16816(acc[mi][2 * nj + 1], a[mi][0], a[mi][1], a[mi][2], a[mi][3],
                             b[nj][2], b[nj][3]);
                }
        }
        if (++s == STAGES) s = 0;
    }

    const int mrow = bm * BM + wm * 64 + (lane >> 2);
    const int ncol = bn * BN + wn * 64 + 2 * (lane & 3);
#pragma unroll
    for (int nj = 0; nj < 8; nj++) {
        int c = ncol + nj * 8;
        float b0 = g_bias[c], b1 = g_bias[c + 1];
#pragma unroll
        for (int mi = 0; mi < 4; mi++) {
            int r0 = mrow + mi * 16;
            float2 v0 = make_float2(acc[mi][nj][0] + b0, acc[mi][nj][1] + b1);
            float2 v1 = make_float2(acc[mi][nj][2] + b0, acc[mi][nj][3] + b1);
            *(float2*)(C + (size_t)r0 * NCAT + c) = v0;
            *(float2*)(C + (size_t)(r0 + 8) * NCAT + c) = v1;
        }
    }
}

// ---------------- packed warp top-32-of-128 ---------------------------------
__device__ __forceinline__ uint32_t ordf(float f) {
    int b = __float_as_int(f);
    return (uint32_t)(b ^ ((b >> 31) | 0x80000000));
}
__device__ __forceinline__ float deordf(uint32_t u) {
    int b = (u & 0x80000000u) ? (int)(u ^ 0x80000000u) : ~(int)u;
    return __int_as_float(b);
}

#define PCEX(v, j, takeMax) do { \
    uint32_t _o = __shfl_xor_sync(0xffffffffu, (v), (j)); \
    (v) = (takeMax) ? ((v) > _o ? (v) : _o) : ((v) < _o ? (v) : _o); \
} while (0)

__device__ __forceinline__ uint32_t top32of128(uint32_t u[4], int lane)
{
#pragma unroll
    for (int k = 2; k <= 32; k <<= 1) {
#pragma unroll
        for (int j = k >> 1; j > 0; j >>= 1) {
            bool flag = (lane & k) == 0;
            bool lower = (lane & j) == 0;
            bool tm = (flag == lower);
#pragma unroll
            for (int r = 0; r < 4; r++) PCEX(u[r], j, tm);
        }
    }
    uint32_t a, b;
    {
        uint32_t o1 = __shfl_xor_sync(0xffffffffu, u[1], 31);
        uint32_t o3 = __shfl_xor_sync(0xffffffffu, u[3], 31);
        a = u[0] > o1 ? u[0] : o1;
        b = u[2] > o3 ? u[2] : o3;
    }
#pragma unroll
    for (int j = 16; j > 0; j >>= 1) {
        bool lower = (lane & j) == 0;
        PCEX(a, j, lower);
        PCEX(b, j, lower);
    }
    uint32_t m;
    {
        uint32_t ob = __shfl_xor_sync(0xffffffffu, b, 31);
        m = a > ob ? a : ob;
    }
#pragma unroll
    for (int j = 16; j > 0; j >>= 1) {
        bool lower = (lane & j) == 0;
        PCEX(m, j, lower);
    }
    return m;   // lane l = (l+1)-th largest
}

// ---------------- fused: top-k + softmax + gather + residual + LayerNorm ----
__global__ __launch_bounds__(192) void pkm_fused(
    const float* __restrict__ Cmat, const float* __restrict__ inp,
    const float* __restrict__ gamma, const float* __restrict__ beta,
    float* __restrict__ out, int t0)
{
    const int t = t0 + blockIdx.x;
    const int tid = threadIdx.x;
    const int wid = tid >> 5, lane = tid & 31;

    __shared__ float wsh[HEADS * KNN];
    __shared__ int   ish[HEADS * KNN];
    __shared__ float red[192];

    // ---- phase 1: per-head top-32 + softmax (warps 0-3) ----
    if (wid < HEADS) {
        const int h = wid;
        const float* Srow = Cmat + (size_t)t * NCAT + V_DIM + h * 256;

        uint32_t u[4];
#pragma unroll
        for (int r = 0; r < 4; r++) {
            int e = r * 32 + lane;
            u[r] = (ordf(Srow[e]) & 0xFFFFFF80u) | (uint32_t)e;
        }
        uint32_t top1 = top32of128(u, lane);
#pragma unroll
        for (int r = 0; r < 4; r++) {
            int e = r * 32 + lane;
            u[r] = (ordf(Srow[128 + e]) & 0xFFFFFF80u) | (uint32_t)e;
        }
        uint32_t top2 = top32of128(u, lane);

#pragma unroll
        for (int r = 0; r < 4; r++) {
            int c = r * 32 + lane;
            int tab = c_tab[c];
            int i = tab >> 5, jj = tab & 31;
            uint32_t k1 = __shfl_sync(0xffffffffu, top1, i);
            uint32_t k2 = __shfl_sync(0xffffffffu, top2, jj);
            float f = deordf(k1 & 0xFFFFFF80u) + deordf(k2 & 0xFFFFFF80u);
            u[r] = (c < 119) ? ((ordf(f) & 0xFFFFFF80u) | (uint32_t)c)
                             : (uint32_t)c;
        }
        uint32_t m = top32of128(u, lane);

        int c = m & 127;
        int tab = c_tab[c];
        int i = tab >> 5, jj = tab & 31;
        uint32_t k1 = __shfl_sync(0xffffffffu, top1, i);
        uint32_t k2 = __shfl_sync(0xffffffffu, top2, jj);
        int idx = (int)(k1 & 127u) * N_KEYS + (int)(k2 & 127u);
        float val = deordf(m & 0xFFFFFF80u);
        float mx = __shfl_sync(0xffffffffu, val, 0);
        float e = expf(val - mx);
        float sum = e;
#pragma unroll
        for (int o = 16; o > 0; o >>= 1) sum += __shfl_xor_sync(0xffffffffu, sum, o);
        wsh[h * KNN + lane] = e / sum;
        ish[h * KNN + lane] = idx;
    }
    __syncthreads();

    // ---- phase 2: gather + residual + LN (all 192 threads) ----
    float4 acc;
    {
        float4 d4 = ((const float4*)(Cmat + (size_t)t * NCAT))[tid];
        float4 r4 = ((const float4*)(inp  + (size_t)t * V_DIM))[tid];
        acc.x = d4.x + r4.x; acc.y = d4.y + r4.y;
        acc.z = d4.z + r4.z; acc.w = d4.w + r4.w;
    }

    float4 acc2 = make_float4(0.f, 0.f, 0.f, 0.f);
#pragma unroll 4
    for (int m = 0; m < HEADS * KNN; m += 2) {
        float w0 = wsh[m];
        ushort4 h0 = ((const ushort4*)(g_vb + (size_t)ish[m] * V_DIM))[tid];
        acc.x += w0 * __int_as_float((uint32_t)h0.x << 16);
        acc.y += w0 * __int_as_float((uint32_t)h0.y << 16);
        acc.z += w0 * __int_as_float((uint32_t)h0.z << 16);
        acc.w += w0 * __int_as_float((uint32_t)h0.w << 16);
        float w1 = wsh[m + 1];
        ushort4 h1 = ((const ushort4*)(g_vb + (size_t)ish[m + 1] * V_DIM))[tid];
        acc2.x += w1 * __int_as_float((uint32_t)h1.x << 16);
        acc2.y += w1 * __int_as_float((uint32_t)h1.y << 16);
        acc2.z += w1 * __int_as_float((uint32_t)h1.z << 16);
        acc2.w += w1 * __int_as_float((uint32_t)h1.w << 16);
    }
    acc.x += acc2.x; acc.y += acc2.y; acc.z += acc2.z; acc.w += acc2.w;

    red[tid] = acc.x + acc.y + acc.z + acc.w;
    __syncthreads();
    if (tid < 64) red[tid] += red[tid + 128];
    __syncthreads();
    if (tid < 64) red[tid] += red[tid + 64];
    __syncthreads();
    if (tid < 32) {
        float v = red[tid] + red[tid + 32];
#pragma unroll
        for (int o = 16; o > 0; o >>= 1) v += __shfl_xor_sync(0xffffffffu, v, o);
        if (tid == 0) red[0] = v;
    }
    __syncthreads();
    float mu = red[0] * (1.0f / V_DIM);
    __syncthreads();

    float dx = acc.x - mu, dy = acc.y - mu, dz = acc.z - mu, dw = acc.w - mu;
    red[tid] = dx * dx + dy * dy + dz * dz + dw * dw;
    __syncthreads();
    if (tid < 64) red[tid] += red[tid + 128];
    __syncthreads();
    if (tid < 64) red[tid] += red[tid + 64];
    __syncthreads();
    if (tid < 32) {
        float v = red[tid] + red[tid + 32];
#pragma unroll
        for (int o = 16; o > 0; o >>= 1) v += __shfl_xor_sync(0xffffffffu, v, o);
        if (tid == 0) red[0] = v;
    }
    __syncthreads();
    float var = red[0] * (1.0f / V_DIM);
    float rstd = rsqrtf(var + 1e-12f);

    float4 g4 = ((const float4*)gamma)[tid];
    float4 b4 = ((const float4*)beta)[tid];
    float4 o4;
    o4.x = dx * rstd * g4.x + b4.x;
    o4.y = dy * rstd * g4.y + b4.y;
    o4.z = dz * rstd * g4.z + b4.z;
    o4.w = dw * rstd * g4.w + b4.w;
    ((float4*)(out + (size_t)t * V_DIM))[tid] = o4;
}

// ---------------- launch ---------------------------------------------------
extern "C" void kernel_launch(void* const* d_in, const int* in_sizes, int n_in,
                              void* d_out, int out_size)
{
    const float* hs     = (const float*)d_in[0];
    const float* inp    = (const float*)d_in[1];
    const float* Wd     = (const float*)d_in[2];
    const float* bd     = (const float*)d_in[3];
    const float* Wq     = (const float*)d_in[4];
    const float* bq     = (const float*)d_in[5];
    const float* keys   = (const float*)d_in[6];
    const float* values = (const float*)d_in[7];
    const float* gamma  = (const float*)d_in[8];
    const float* beta   = (const float*)d_in[9];
    float* out = (float*)d_out;

    void* p_C;
    cudaGetSymbolAddress(&p_C, g_C);
    float* C = (float*)p_C;

    cudaFuncSetAttribute(gemm_hmma, cudaFuncAttributeMaxDynamicSharedMemorySize, SMEM_TOTAL);
    cudaFuncSetAttribute(prep_misc, cudaFuncAttributeMaxDynamicSharedMemorySize, PREP_SMEM);

    // one-time stream/event setup (host-side API only; no device memory)
    static cudaStream_t s_aux = nullptr;
    static cudaEvent_t evG[MCHUNKS], evE;
    if (!s_aux) {
        cudaStreamCreateWithFlags(&s_aux, cudaStreamNonBlocking);
        for (int c = 0; c < MCHUNKS; c++)
            cudaEventCreateWithFlags(&evG[c], cudaEventDisableTiming);
        cudaEventCreateWithFlags(&evE, cudaEventDisableTiming);
    }

    // prep (capture/default stream; gemm chunk 0 is the 4th launch = ncu slot)
    split_trans<<<49152 + 2304, 256>>>(hs, Wd);
    prep_misc<<<197, 256, PREP_SMEM>>>(Wq, keys, bd, bq);
    cvt_values<<<(N_KEYS * N_KEYS * V_DIM / 4) / 256, 256>>>(values);

    // pipelined GEMM chunks (default stream) + pkm chunks (side stream)
    for (int c = 0; c < MCHUNKS; c++) {
        gemm_hmma<<<dim3(NCAT / BN, BM_PER_CHUNK), 128, SMEM_TOTAL>>>(
            C, c * BM_PER_CHUNK);
        cudaEventRecord(evG[c], 0);
        cudaStreamWaitEvent(s_aux, evG[c], 0);
        pkm_fused<<<TOK_PER_CHUNK, 192, 0, s_aux>>>(
            C, inp, gamma, beta, out, c * TOK_PER_CHUNK);
    }
    cudaEventRecord(evE, s_aux);
    cudaStreamWaitEvent(0, evE, 0);
}

// round 15
// speedup vs baseline: 1.1435x; 1.1435x over previous
#include <cuda_runtime.h>
#include <cuda_fp16.h>
#include <cuda_bf16.h>
#include <math.h>
#include <float.h>
#include <stdint.h>

#define T_TOT   16384
#define IN_DIM  3072
#define V_DIM   768
#define HEADS   4
#define KNN     32
#define N_KEYS  128
#define NCAT    1792            // 768 (dense) + 1024 (scores)
#define BM      128
#define BN      128
#define BK      64
#define STAGES  3
#define NCHUNK  48              // IN_DIM / BK
#define STAGE_BYTES (BM * BK * 2 + BN * BK * 2)   // 32768
#define SMEM_TOTAL  (STAGES * STAGE_BYTES)        // 98304
#define PREP_SMEM   (128 * 132 * 4 + 128 * 128 * 4)  // 133120
#define MCHUNKS 2
#define BM_PER_CHUNK (T_TOT / BM / MCHUNKS)       // 64
#define TOK_PER_CHUNK (T_TOT / MCHUNKS)           // 8192

// ---------------- scratch (device globals; no allocation allowed) ----------
__device__ __align__(256) __half g_Ah[(size_t)T_TOT * IN_DIM];
__device__ __align__(256) __half g_Bh[(size_t)NCAT * IN_DIM];
__device__ __align__(256) float g_bias[NCAT];
__device__ __align__(256) float g_C[(size_t)T_TOT * NCAT];
__device__ __align__(256) __nv_bfloat16 g_vb[(size_t)(N_KEYS * N_KEYS) * V_DIM];

// pruned product-key candidate table: (i<<5)|j for all (i+1)*(j+1) <= 32
__constant__ unsigned short c_tab[128] = {
    0,1,2,3,4,5,6,7,8,9,10,11,12,13,14,15,
    16,17,18,19,20,21,22,23,24,25,26,27,28,29,30,31,
    32,33,34,35,36,37,38,39,40,41,42,43,44,45,46,47,
    64,65,66,67,68,69,70,71,72,73,
    96,97,98,99,100,101,102,103,
    128,129,130,131,132,133,
    160,161,162,163,164,
    192,193,194,195,
    224,225,226,227,
    256,257,258,
    288,289,290,
    320,321, 352,353, 384,385, 416,417, 448,449, 480,481,
    512,544,576,608,640,672,704,736,768,800,832,864,896,928,960,992,
    0,0,0,0,0,0,0,0,0
};

// ---------------- PTX helpers ----------------------------------------------
__device__ __forceinline__ uint32_t smem_u32(const void* p) {
    uint32_t a;
    asm("{ .reg .u64 t; cvta.to.shared.u64 t, %1; cvt.u32.u64 %0, t; }" : "=r"(a) : "l"(p));
    return a;
}
#define SW128(off) ((off) ^ (((off) >> 3) & 0x70))

__device__ __forceinline__ void cp_async16(uint32_t dst, const void* src) {
    asm volatile("cp.async.cg.shared.global [%0], [%1], 16;" :: "r"(dst), "l"(src));
}
#define CP_COMMIT() asm volatile("cp.async.commit_group;" ::: "memory")
#define CP_WAIT1()  asm volatile("cp.async.wait_group 1;" ::: "memory")

#define LDSM4(r0, r1, r2, r3, addr) \
    asm volatile("ldmatrix.sync.aligned.m8n8.x4.shared.b16 {%0,%1,%2,%3}, [%4];" \
                 : "=r"(r0), "=r"(r1), "=r"(r2), "=r"(r3) : "r"(addr))

#define MMA16816(d, a0, a1, a2, a3, b0, b1) \
    asm volatile("mma.sync.aligned.m16n8k16.row.col.f32.f16.f16.f32 " \
                 "{%0,%1,%2,%3}, {%4,%5,%6,%7}, {%8,%9}, {%0,%1,%2,%3};" \
                 : "+f"((d)[0]), "+f"((d)[1]), "+f"((d)[2]), "+f"((d)[3]) \
                 : "r"(a0), "r"(a1), "r"(a2), "r"(a3), "r"(b0), "r"(b1))

// ---------------- prep: A -> fp16 + transpose W_dense -----------------------
__global__ __launch_bounds__(256) void split_trans(
    const float* __restrict__ X, const float* __restrict__ W)
{
    __shared__ float tile[32][33];
    const int b = blockIdx.x, t = threadIdx.x;
    if (b < 49152) {
        size_t i = (size_t)b * 256 + t;          // one float4
        float4 v = ((const float4*)X)[i];
        ushort4 h;
        h.x = __half_as_ushort(__float2half_rn(v.x));
        h.y = __half_as_ushort(__float2half_rn(v.y));
        h.z = __half_as_ushort(__float2half_rn(v.z));
        h.w = __half_as_ushort(__float2half_rn(v.w));
        ((ushort4*)g_Ah)[i] = h;
    } else {
        const int b2 = b - 49152;
        const int n0 = (b2 % 24) * 32, k0 = (b2 / 24) * 32;
        const int tx = t & 31, ty = t >> 5;
#pragma unroll
        for (int j = 0; j < 32; j += 8)
            tile[ty + j][tx] = W[(size_t)(k0 + ty + j) * V_DIM + n0 + tx];
        __syncthreads();
#pragma unroll
        for (int j = 0; j < 32; j += 8) {
            int n = n0 + ty + j, k = k0 + tx;
            g_Bh[(size_t)n * IN_DIM + k] = __float2half_rn(tile[tx][ty + j]);
        }
    }
}

// merged: W_keff = Wq x keys^T (rows 768..1791 of g_Bh), score bias, dense bias
// register-tiled: 64 accumulators/thread, float4 smem reads (FMA-bound)
__global__ __launch_bounds__(256) void prep_misc(
    const float* __restrict__ Wq, const float* __restrict__ keys,
    const float* __restrict__ bd, const float* __restrict__ bq)
{
    extern __shared__ float sm[];
    float (*Ws)[132] = (float(*)[132])sm;                 // [kloc][d] padded
    float (*Ks)[128] = (float(*)[128])(sm + 128 * 132);   // [n][d]
    const int b = blockIdx.x, t = threadIdx.x;

    if (b < 192) {
        const int hs = b & 7, kt = b >> 3;
        for (int i = t; i < 128 * 128; i += 256) {
            int r = i >> 7, d = i & 127;
            Ws[r][d] = Wq[(size_t)(kt * 128 + r) * 1024 + hs * 128 + d];
            Ks[r][d] = keys[(size_t)(hs * 128 + r) * 128 + d];
        }
        __syncthreads();
        const int kloc = t & 127, nh = t >> 7;
        float acc[64];
#pragma unroll
        for (int no = 0; no < 64; no++) acc[no] = 0.f;
        for (int d4 = 0; d4 < 128; d4 += 4) {
            float4 ws = *(const float4*)&Ws[kloc][d4];
#pragma unroll 16
            for (int no = 0; no < 64; no++) {
                float4 ks = *(const float4*)&Ks[nh * 64 + no][d4];
                acc[no] += ws.x * ks.x + ws.y * ks.y + ws.z * ks.z + ws.w * ks.w;
            }
        }
        for (int no = 0; no < 64; no++)
            g_Bh[(size_t)(V_DIM + hs * 128 + nh * 64 + no) * IN_DIM + kt * 128 + kloc] =
                __float2half_rn(acc[no]);
    } else if (b < 196) {
        int np = (b - 192) * 256 + t;     // 0..1023
        int hs = np >> 7, n = np & 127;
        float acc = 0.f;
        for (int d = 0; d < 128; d++)
            acc += bq[hs * 128 + d] * keys[(size_t)(hs * 128 + n) * 128 + d];
        g_bias[V_DIM + np] = acc;
    } else {
        for (int i = t; i < V_DIM; i += 256) g_bias[i] = bd[i];
    }
}

// ---------------- values table -> bf16 --------------------------------------
__global__ __launch_bounds__(256) void cvt_values(const float* __restrict__ v)
{
    size_t i = (size_t)blockIdx.x * 256 + threadIdx.x;   // one float4
    float4 x = ((const float4*)v)[i];
    ushort4 o;
    o.x = __bfloat16_as_ushort(__float2bfloat16(x.x));
    o.y = __bfloat16_as_ushort(__float2bfloat16(x.y));
    o.z = __bfloat16_as_ushort(__float2bfloat16(x.z));
    o.w = __bfloat16_as_ushort(__float2bfloat16(x.w));
    ((ushort4*)g_vb)[i] = o;
}

// ---------------- HMMA GEMM: 128x128 CTA tile, 64x64 warp tile, 2 CTA/SM ---
__device__ __forceinline__ void load_chunk(
    int chunk, int s, int tid, int bm, int bn, uint32_t sb)
{
    int k0 = chunk * BK;
    const __half* Ag = g_Ah + (size_t)(bm * BM) * IN_DIM + k0;
    const __half* Bg = g_Bh + (size_t)(bn * BN) * IN_DIM + k0;
    uint32_t sA = sb + s * STAGE_BYTES;
    uint32_t sB = sA + BM * BK * 2;
#pragma unroll
    for (int it = 0; it < 8; it++) {      // A: 1024 x 16B over 128 threads
        int u = tid + it * 128;
        int r = u >> 3, ch = u & 7;
        cp_async16(sA + SW128(r * 128 + ch * 16), Ag + (size_t)r * IN_DIM + ch * 8);
    }
#pragma unroll
    for (int it = 0; it < 8; it++) {      // B: 1024 x 16B
        int u = tid + it * 128;
        int r = u >> 3, ch = u & 7;
        cp_async16(sB + SW128(r * 128 + ch * 16), Bg + (size_t)r * IN_DIM + ch * 8);
    }
}

__global__ __launch_bounds__(128, 2) void gemm_hmma(float* __restrict__ C, int bm0)
{
    extern __shared__ char smem[];
    uint32_t sb = smem_u32(smem);
    const int tid = threadIdx.x, wid = tid >> 5, lane = tid & 31;
    const int bn = blockIdx.x, bm = bm0 + blockIdx.y;
    const int wm = wid & 1;          // M half: rows wm*64
    const int wn = wid >> 1;         // N half: cols wn*64

    float acc[4][8][4];
#pragma unroll
    for (int a = 0; a < 4; a++)
#pragma unroll
        for (int b = 0; b < 8; b++)
#pragma unroll
            for (int c = 0; c < 4; c++) acc[a][b][c] = 0.f;

    const int sub = lane >> 3, lr = lane & 7;
    const int arow0 = wm * 64 + ((sub & 1) << 3) + lr;   // + mi*16
    const int akc = sub >> 1;
    const int brow0 = wn * 64 + ((sub >> 1) << 3) + lr;  // + nj*16
    const int bkc = sub & 1;

#pragma unroll
    for (int s = 0; s < STAGES - 1; s++) {
        load_chunk(s, s, tid, bm, bn, sb);
        CP_COMMIT();
    }

    int s = 0;
    for (int i = 0; i < NCHUNK; i++) {
        CP_WAIT1();
        __syncthreads();
        const int nc = i + STAGES - 1;
        if (nc < NCHUNK) {
            int sp = s + STAGES - 1; if (sp >= STAGES) sp -= STAGES;
            load_chunk(nc, sp, tid, bm, bn, sb);
        }
        CP_COMMIT();

        const uint32_t sA = sb + s * STAGE_BYTES;
        const uint32_t sB = sA + BM * BK * 2;
#pragma unroll
        for (int ks = 0; ks < 4; ks++) {
            uint32_t a[4][4];
#pragma unroll
            for (int mi = 0; mi < 4; mi++) {
                int row = arow0 + mi * 16;
                uint32_t ad = sA + row * 128 + (((2 * ks + akc) ^ (row & 7)) << 4);
                LDSM4(a[mi][0], a[mi][1], a[mi][2], a[mi][3], ad);
            }
            uint32_t b[4][4];
#pragma unroll
            for (int nj = 0; nj < 4; nj++) {
                int row = brow0 + nj * 16;
                uint32_t bd = sB + row * 128 + (((2 * ks + bkc) ^ (row & 7)) << 4);
                LDSM4(b[nj][0], b[nj][1], b[nj][2], b[nj][3], bd);
            }
#pragma unroll
            for (int mi = 0; mi < 4; mi++)
#pragma unroll
                for (int nj = 0; nj < 4; nj++) {
                    MMA16816(acc[mi][2 * nj],     a[mi][0], a[mi][1], a[mi][2], a[mi][3],
                             b[nj][0], b[nj][1]);
                    MMA16816(acc[mi][2 * nj + 1], a[mi][0], a[mi][1], a[mi][2], a[mi][3],
                             b[nj][2], b[nj][3]);
                }
        }
        if (++s == STAGES) s = 0;
    }

    const int mrow = bm * BM + wm * 64 + (lane >> 2);
    const int ncol = bn * BN + wn * 64 + 2 * (lane & 3);
#pragma unroll
    for (int nj = 0; nj < 8; nj++) {
        int c = ncol + nj * 8;
        float b0 = g_bias[c], b1 = g_bias[c + 1];
#pragma unroll
        for (int mi = 0; mi < 4; mi++) {
            int r0 = mrow + mi * 16;
            float2 v0 = make_float2(acc[mi][nj][0] + b0, acc[mi][nj][1] + b1);
            float2 v1 = make_float2(acc[mi][nj][2] + b0, acc[mi][nj][3] + b1);
            *(float2*)(C + (size_t)r0 * NCAT + c) = v0;
            *(float2*)(C + (size_t)(r0 + 8) * NCAT + c) = v1;
        }
    }
}

// ---------------- packed warp top-32-of-128 ---------------------------------
__device__ __forceinline__ uint32_t ordf(float f) {
    int b = __float_as_int(f);
    return (uint32_t)(b ^ ((b >> 31) | 0x80000000));
}
__device__ __forceinline__ float deordf(uint32_t u) {
    int b = (u & 0x80000000u) ? (int)(u ^ 0x80000000u) : ~(int)u;
    return __int_as_float(b);
}

#define PCEX(v, j, takeMax) do { \
    uint32_t _o = __shfl_xor_sync(0xffffffffu, (v), (j)); \
    (v) = (takeMax) ? ((v) > _o ? (v) : _o) : ((v) < _o ? (v) : _o); \
} while (0)

__device__ __forceinline__ uint32_t top32of128(uint32_t u[4], int lane)
{
#pragma unroll
    for (int k = 2; k <= 32; k <<= 1) {
#pragma unroll
        for (int j = k >> 1; j > 0; j >>= 1) {
            bool flag = (lane & k) == 0;
            bool lower = (lane & j) == 0;
            bool tm = (flag == lower);
#pragma unroll
            for (int r = 0; r < 4; r++) PCEX(u[r], j, tm);
        }
    }
    uint32_t a, b;
    {
        uint32_t o1 = __shfl_xor_sync(0xffffffffu, u[1], 31);
        uint32_t o3 = __shfl_xor_sync(0xffffffffu, u[3], 31);
        a = u[0] > o1 ? u[0] : o1;
        b = u[2] > o3 ? u[2] : o3;
    }
#pragma unroll
    for (int j = 16; j > 0; j >>= 1) {
        bool lower = (lane & j) == 0;
        PCEX(a, j, lower);
        PCEX(b, j, lower);
    }
    uint32_t m;
    {
        uint32_t ob = __shfl_xor_sync(0xffffffffu, b, 31);
        m = a > ob ? a : ob;
    }
#pragma unroll
    for (int j = 16; j > 0; j >>= 1) {
        bool lower = (lane & j) == 0;
        PCEX(m, j, lower);
    }
    return m;   // lane l = (l+1)-th largest
}

// ---------------- fused: top-k + softmax + gather + residual + LayerNorm ----
__global__ __launch_bounds__(192) void pkm_fused(
    const float* __restrict__ Cmat, const float* __restrict__ inp,
    const float* __restrict__ gamma, const float* __restrict__ beta,
    float* __restrict__ out, int t0)
{
    const int t = t0 + blockIdx.x;
    const int tid = threadIdx.x;
    const int wid = tid >> 5, lane = tid & 31;

    __shared__ float wsh[HEADS * KNN];
    __shared__ int   ish[HEADS * KNN];
    __shared__ float red[192];

    // ---- phase 1: per-head top-32 + softmax (warps 0-3) ----
    if (wid < HEADS) {
        const int h = wid;
        const float* Srow = Cmat + (size_t)t * NCAT + V_DIM + h * 256;

        uint32_t u[4];
#pragma unroll
        for (int r = 0; r < 4; r++) {
            int e = r * 32 + lane;
            u[r] = (ordf(Srow[e]) & 0xFFFFFF80u) | (uint32_t)e;
        }
        uint32_t top1 = top32of128(u, lane);
#pragma unroll
        for (int r = 0; r < 4; r++) {
            int e = r * 32 + lane;
            u[r] = (ordf(Srow[128 + e]) & 0xFFFFFF80u) | (uint32_t)e;
        }
        uint32_t top2 = top32of128(u, lane);

#pragma unroll
        for (int r = 0; r < 4; r++) {
            int c = r * 32 + lane;
            int tab = c_tab[c];
            int i = tab >> 5, jj = tab & 31;
            uint32_t k1 = __shfl_sync(0xffffffffu, top1, i);
            uint32_t k2 = __shfl_sync(0xffffffffu, top2, jj);
            float f = deordf(k1 & 0xFFFFFF80u) + deordf(k2 & 0xFFFFFF80u);
            u[r] = (c < 119) ? ((ordf(f) & 0xFFFFFF80u) | (uint32_t)c)
                             : (uint32_t)c;
        }
        uint32_t m = top32of128(u, lane);

        int c = m & 127;
        int tab = c_tab[c];
        int i = tab >> 5, jj = tab & 31;
        uint32_t k1 = __shfl_sync(0xffffffffu, top1, i);
        uint32_t k2 = __shfl_sync(0xffffffffu, top2, jj);
        int idx = (int)(k1 & 127u) * N_KEYS + (int)(k2 & 127u);
        float val = deordf(m & 0xFFFFFF80u);
        float mx = __shfl_sync(0xffffffffu, val, 0);
        float e = expf(val - mx);
        float sum = e;
#pragma unroll
        for (int o = 16; o > 0; o >>= 1) sum += __shfl_xor_sync(0xffffffffu, sum, o);
        wsh[h * KNN + lane] = e / sum;
        ish[h * KNN + lane] = idx;
    }
    __syncthreads();

    // ---- phase 2: gather + residual + LN (all 192 threads) ----
    float4 acc;
    {
        float4 d4 = ((const float4*)(Cmat + (size_t)t * NCAT))[tid];
        float4 r4 = ((const float4*)(inp  + (size_t)t * V_DIM))[tid];
        acc.x = d4.x + r4.x; acc.y = d4.y + r4.y;
        acc.z = d4.z + r4.z; acc.w = d4.w + r4.w;
    }

    float4 acc2 = make_float4(0.f, 0.f, 0.f, 0.f);
#pragma unroll 4
    for (int m = 0; m < HEADS * KNN; m += 2) {
        float w0 = wsh[m];
        ushort4 h0 = ((const ushort4*)(g_vb + (size_t)ish[m] * V_DIM))[tid];
        acc.x += w0 * __int_as_float((uint32_t)h0.x << 16);
        acc.y += w0 * __int_as_float((uint32_t)h0.y << 16);
        acc.z += w0 * __int_as_float((uint32_t)h0.z << 16);
        acc.w += w0 * __int_as_float((uint32_t)h0.w << 16);
        float w1 = wsh[m + 1];
        ushort4 h1 = ((const ushort4*)(g_vb + (size_t)ish[m + 1] * V_DIM))[tid];
        acc2.x += w1 * __int_as_float((uint32_t)h1.x << 16);
        acc2.y += w1 * __int_as_float((uint32_t)h1.y << 16);
        acc2.z += w1 * __int_as_float((uint32_t)h1.z << 16);
        acc2.w += w1 * __int_as_float((uint32_t)h1.w << 16);
    }
    acc.x += acc2.x; acc.y += acc2.y; acc.z += acc2.z; acc.w += acc2.w;

    red[tid] = acc.x + acc.y + acc.z + acc.w;
    __syncthreads();
    if (tid < 64) red[tid] += red[tid + 128];
    __syncthreads();
    if (tid < 64) red[tid] += red[tid + 64];
    __syncthreads();
    if (tid < 32) {
        float v = red[tid] + red[tid + 32];
#pragma unroll
        for (int o = 16; o > 0; o >>= 1) v += __shfl_xor_sync(0xffffffffu, v, o);
        if (tid == 0) red[0] = v;
    }
    __syncthreads();
    float mu = red[0] * (1.0f / V_DIM);
    __syncthreads();

    float dx = acc.x - mu, dy = acc.y - mu, dz = acc.z - mu, dw = acc.w - mu;
    red[tid] = dx * dx + dy * dy + dz * dz + dw * dw;
    __syncthreads();
    if (tid < 64) red[tid] += red[tid + 128];
    __syncthreads();
    if (tid < 64) red[tid] += red[tid + 64];
    __syncthreads();
    if (tid < 32) {
        float v = red[tid] + red[tid + 32];
#pragma unroll
        for (int o = 16; o > 0; o >>= 1) v += __shfl_xor_sync(0xffffffffu, v, o);
        if (tid == 0) red[0] = v;
    }
    __syncthreads();
    float var = red[0] * (1.0f / V_DIM);
    float rstd = rsqrtf(var + 1e-12f);

    float4 g4 = ((const float4*)gamma)[tid];
    float4 b4 = ((const float4*)beta)[tid];
    float4 o4;
    o4.x = dx * rstd * g4.x + b4.x;
    o4.y = dy * rstd * g4.y + b4.y;
    o4.z = dz * rstd * g4.z + b4.z;
    o4.w = dw * rstd * g4.w + b4.w;
    ((float4*)(out + (size_t)t * V_DIM))[tid] = o4;
}

// ---------------- launch ---------------------------------------------------
extern "C" void kernel_launch(void* const* d_in, const int* in_sizes, int n_in,
                              void* d_out, int out_size)
{
    const float* hs     = (const float*)d_in[0];
    const float* inp    = (const float*)d_in[1];
    const float* Wd     = (const float*)d_in[2];
    const float* bd     = (const float*)d_in[3];
    const float* Wq     = (const float*)d_in[4];
    const float* bq     = (const float*)d_in[5];
    const float* keys   = (const float*)d_in[6];
    const float* values = (const float*)d_in[7];
    const float* gamma  = (const float*)d_in[8];
    const float* beta   = (const float*)d_in[9];
    float* out = (float*)d_out;

    void* p_C;
    cudaGetSymbolAddress(&p_C, g_C);
    float* C = (float*)p_C;

    cudaFuncSetAttribute(gemm_hmma, cudaFuncAttributeMaxDynamicSharedMemorySize, SMEM_TOTAL);
    cudaFuncSetAttribute(prep_misc, cudaFuncAttributeMaxDynamicSharedMemorySize, PREP_SMEM);

    // one-time stream/event setup (host-side API only; no device memory)
    static cudaStream_t s_aux = nullptr;
    static cudaEvent_t evG[MCHUNKS], evE;
    if (!s_aux) {
        cudaStreamCreateWithFlags(&s_aux, cudaStreamNonBlocking);
        for (int c = 0; c < MCHUNKS; c++)
            cudaEventCreateWithFlags(&evG[c], cudaEventDisableTiming);
        cudaEventCreateWithFlags(&evE, cudaEventDisableTiming);
    }

    // prep (capture/default stream; gemm chunk 0 is the 4th launch = ncu slot)
    split_trans<<<49152 + 2304, 256>>>(hs, Wd);
    prep_misc<<<197, 256, PREP_SMEM>>>(Wq, keys, bd, bq);
    cvt_values<<<(N_KEYS * N_KEYS * V_DIM / 4) / 256, 256>>>(values);

    // pipelined GEMM halves (default stream) + pkm halves (side stream)
    for (int c = 0; c < MCHUNKS; c++) {
        gemm_hmma<<<dim3(NCAT / BN, BM_PER_CHUNK), 128, SMEM_TOTAL>>>(
            C, c * BM_PER_CHUNK);
        cudaEventRecord(evG[c], 0);
        cudaStreamWaitEvent(s_aux, evG[c], 0);
        pkm_fused<<<TOK_PER_CHUNK, 192, 0, s_aux>>>(
            C, inp, gamma, beta, out, c * TOK_PER_CHUNK);
    }
    cudaEventRecord(evE, s_aux);
    cudaStreamWaitEvent(0, evE, 0);
}

// round 16
// speedup vs baseline: 1.1660x; 1.0196x over previous
#include <cuda_runtime.h>
#include <cuda_fp16.h>
#include <cuda_bf16.h>
#include <math.h>
#include <float.h>
#include <stdint.h>

#define T_TOT   16384
#define IN_DIM  3072
#define V_DIM   768
#define HEADS   4
#define KNN     32
#define N_KEYS  128
#define NCAT    1792            // 768 (dense) + 1024 (scores)
#define BM      128
#define BN      128
#define BK      64
#define STAGES  3
#define NCHUNK  48              // IN_DIM / BK
#define STAGE_BYTES (BM * BK * 2 + BN * BK * 2)   // 32768
#define SMEM_TOTAL  (STAGES * STAGE_BYTES)        // 98304
#define PREP_SMEM   (128 * 132 * 4 + 128 * 128 * 4)  // 133120

// ---------------- scratch (device globals; no allocation allowed) ----------
__device__ __align__(256) __half g_Ah[(size_t)T_TOT * IN_DIM];
__device__ __align__(256) __half g_Bh[(size_t)NCAT * IN_DIM];
__device__ __align__(256) float g_bias[NCAT];
__device__ __align__(256) float g_C[(size_t)T_TOT * NCAT];
__device__ __align__(256) __nv_bfloat16 g_vb[(size_t)(N_KEYS * N_KEYS) * V_DIM];

// pruned product-key candidate table: (i<<5)|j for all (i+1)*(j+1) <= 32
__constant__ unsigned short c_tab[128] = {
    0,1,2,3,4,5,6,7,8,9,10,11,12,13,14,15,
    16,17,18,19,20,21,22,23,24,25,26,27,28,29,30,31,
    32,33,34,35,36,37,38,39,40,41,42,43,44,45,46,47,
    64,65,66,67,68,69,70,71,72,73,
    96,97,98,99,100,101,102,103,
    128,129,130,131,132,133,
    160,161,162,163,164,
    192,193,194,195,
    224,225,226,227,
    256,257,258,
    288,289,290,
    320,321, 352,353, 384,385, 416,417, 448,449, 480,481,
    512,544,576,608,640,672,704,736,768,800,832,864,896,928,960,992,
    0,0,0,0,0,0,0,0,0
};

// ---------------- PTX helpers ----------------------------------------------
__device__ __forceinline__ uint32_t smem_u32(const void* p) {
    uint32_t a;
    asm("{ .reg .u64 t; cvta.to.shared.u64 t, %1; cvt.u32.u64 %0, t; }" : "=r"(a) : "l"(p));
    return a;
}
#define SW128(off) ((off) ^ (((off) >> 3) & 0x70))

__device__ __forceinline__ void cp_async16(uint32_t dst, const void* src) {
    asm volatile("cp.async.cg.shared.global [%0], [%1], 16;" :: "r"(dst), "l"(src));
}
#define CP_COMMIT() asm volatile("cp.async.commit_group;" ::: "memory")
#define CP_WAIT1()  asm volatile("cp.async.wait_group 1;" ::: "memory")

#define LDSM4(r0, r1, r2, r3, addr) \
    asm volatile("ldmatrix.sync.aligned.m8n8.x4.shared.b16 {%0,%1,%2,%3}, [%4];" \
                 : "=r"(r0), "=r"(r1), "=r"(r2), "=r"(r3) : "r"(addr))

#define MMA16816(d, a0, a1, a2, a3, b0, b1) \
    asm volatile("mma.sync.aligned.m16n8k16.row.col.f32.f16.f16.f32 " \
                 "{%0,%1,%2,%3}, {%4,%5,%6,%7}, {%8,%9}, {%0,%1,%2,%3};" \
                 : "+f"((d)[0]), "+f"((d)[1]), "+f"((d)[2]), "+f"((d)[3]) \
                 : "r"(a0), "r"(a1), "r"(a2), "r"(a3), "r"(b0), "r"(b1))

// ---------------- prep: A -> fp16 + transpose W_dense -----------------------
__global__ __launch_bounds__(256) void split_trans(
    const float* __restrict__ X, const float* __restrict__ W)
{
    __shared__ float tile[32][33];
    const int b = blockIdx.x, t = threadIdx.x;
    if (b < 49152) {
        size_t i = (size_t)b * 256 + t;          // one float4
        float4 v = ((const float4*)X)[i];
        ushort4 h;
        h.x = __half_as_ushort(__float2half_rn(v.x));
        h.y = __half_as_ushort(__float2half_rn(v.y));
        h.z = __half_as_ushort(__float2half_rn(v.z));
        h.w = __half_as_ushort(__float2half_rn(v.w));
        ((ushort4*)g_Ah)[i] = h;
    } else {
        const int b2 = b - 49152;
        const int n0 = (b2 % 24) * 32, k0 = (b2 / 24) * 32;
        const int tx = t & 31, ty = t >> 5;
#pragma unroll
        for (int j = 0; j < 32; j += 8)
            tile[ty + j][tx] = W[(size_t)(k0 + ty + j) * V_DIM + n0 + tx];
        __syncthreads();
#pragma unroll
        for (int j = 0; j < 32; j += 8) {
            int n = n0 + ty + j, k = k0 + tx;
            g_Bh[(size_t)n * IN_DIM + k] = __float2half_rn(tile[tx][ty + j]);
        }
    }
}

// merged: W_keff = Wq x keys^T (rows 768..1791 of g_Bh), score bias, dense bias
// register-tiled: 64 accumulators/thread, float4 smem reads (FMA-bound)
__global__ __launch_bounds__(256) void prep_misc(
    const float* __restrict__ Wq, const float* __restrict__ keys,
    const float* __restrict__ bd, const float* __restrict__ bq)
{
    extern __shared__ float sm[];
    float (*Ws)[132] = (float(*)[132])sm;                 // [kloc][d] padded
    float (*Ks)[128] = (float(*)[128])(sm + 128 * 132);   // [n][d]
    const int b = blockIdx.x, t = threadIdx.x;

    if (b < 192) {
        const int hs = b & 7, kt = b >> 3;
        for (int i = t; i < 128 * 128; i += 256) {
            int r = i >> 7, d = i & 127;
            Ws[r][d] = Wq[(size_t)(kt * 128 + r) * 1024 + hs * 128 + d];
            Ks[r][d] = keys[(size_t)(hs * 128 + r) * 128 + d];
        }
        __syncthreads();
        const int kloc = t & 127, nh = t >> 7;
        float acc[64];
#pragma unroll
        for (int no = 0; no < 64; no++) acc[no] = 0.f;
        for (int d4 = 0; d4 < 128; d4 += 4) {
            float4 ws = *(const float4*)&Ws[kloc][d4];
#pragma unroll 16
            for (int no = 0; no < 64; no++) {
                float4 ks = *(const float4*)&Ks[nh * 64 + no][d4];
                acc[no] += ws.x * ks.x + ws.y * ks.y + ws.z * ks.z + ws.w * ks.w;
            }
        }
        for (int no = 0; no < 64; no++)
            g_Bh[(size_t)(V_DIM + hs * 128 + nh * 64 + no) * IN_DIM + kt * 128 + kloc] =
                __float2half_rn(acc[no]);
    } else if (b < 196) {
        int np = (b - 192) * 256 + t;     // 0..1023
        int hs = np >> 7, n = np & 127;
        float acc = 0.f;
        for (int d = 0; d < 128; d++)
            acc += bq[hs * 128 + d] * keys[(size_t)(hs * 128 + n) * 128 + d];
        g_bias[V_DIM + np] = acc;
    } else {
        for (int i = t; i < V_DIM; i += 256) g_bias[i] = bd[i];
    }
}

// ---------------- values table -> bf16 --------------------------------------
__global__ __launch_bounds__(256) void cvt_values(const float* __restrict__ v)
{
    size_t i = (size_t)blockIdx.x * 256 + threadIdx.x;   // one float4
    float4 x = ((const float4*)v)[i];
    ushort4 o;
    o.x = __bfloat16_as_ushort(__float2bfloat16(x.x));
    o.y = __bfloat16_as_ushort(__float2bfloat16(x.y));
    o.z = __bfloat16_as_ushort(__float2bfloat16(x.z));
    o.w = __bfloat16_as_ushort(__float2bfloat16(x.w));
    ((ushort4*)g_vb)[i] = o;
}

// ---------------- HMMA GEMM: 128x128 CTA tile, 64x64 warp tile, 2 CTA/SM ---
__device__ __forceinline__ void load_chunk(
    int chunk, int s, int tid, int bm, int bn, uint32_t sb)
{
    int k0 = chunk * BK;
    const __half* Ag = g_Ah + (size_t)(bm * BM) * IN_DIM + k0;
    const __half* Bg = g_Bh + (size_t)(bn * BN) * IN_DIM + k0;
    uint32_t sA = sb + s * STAGE_BYTES;
    uint32_t sB = sA + BM * BK * 2;
#pragma unroll
    for (int it = 0; it < 8; it++) {      // A: 1024 x 16B over 128 threads
        int u = tid + it * 128;
        int r = u >> 3, ch = u & 7;
        cp_async16(sA + SW128(r * 128 + ch * 16), Ag + (size_t)r * IN_DIM + ch * 8);
    }
#pragma unroll
    for (int it = 0; it < 8; it++) {      // B: 1024 x 16B
        int u = tid + it * 128;
        int r = u >> 3, ch = u & 7;
        cp_async16(sB + SW128(r * 128 + ch * 16), Bg + (size_t)r * IN_DIM + ch * 8);
    }
}

__global__ __launch_bounds__(128, 2) void gemm_hmma(float* __restrict__ C)
{
    extern __shared__ char smem[];
    uint32_t sb = smem_u32(smem);
    const int tid = threadIdx.x, wid = tid >> 5, lane = tid & 31;
    const int bn = blockIdx.x, bm = blockIdx.y;
    const int wm = wid & 1;          // M half: rows wm*64
    const int wn = wid >> 1;         // N half: cols wn*64

    float acc[4][8][4];
#pragma unroll
    for (int a = 0; a < 4; a++)
#pragma unroll
        for (int b = 0; b < 8; b++)
#pragma unroll
            for (int c = 0; c < 4; c++) acc[a][b][c] = 0.f;

    const int sub = lane >> 3, lr = lane & 7;
    const int arow0 = wm * 64 + ((sub & 1) << 3) + lr;   // + mi*16
    const int akc = sub >> 1;
    const int brow0 = wn * 64 + ((sub >> 1) << 3) + lr;  // + nj*16
    const int bkc = sub & 1;

#pragma unroll
    for (int s = 0; s < STAGES - 1; s++) {
        load_chunk(s, s, tid, bm, bn, sb);
        CP_COMMIT();
    }

    int s = 0;
    for (int i = 0; i < NCHUNK; i++) {
        CP_WAIT1();
        __syncthreads();
        const int nc = i + STAGES - 1;
        if (nc < NCHUNK) {
            int sp = s + STAGES - 1; if (sp >= STAGES) sp -= STAGES;
            load_chunk(nc, sp, tid, bm, bn, sb);
        }
        CP_COMMIT();

        const uint32_t sA = sb + s * STAGE_BYTES;
        const uint32_t sB = sA + BM * BK * 2;
#pragma unroll
        for (int ks = 0; ks < 4; ks++) {
            uint32_t a[4][4];
#pragma unroll
            for (int mi = 0; mi < 4; mi++) {
                int row = arow0 + mi * 16;
                uint32_t ad = sA + row * 128 + (((2 * ks + akc) ^ (row & 7)) << 4);
                LDSM4(a[mi][0], a[mi][1], a[mi][2], a[mi][3], ad);
            }
            uint32_t b[4][4];
#pragma unroll
            for (int nj = 0; nj < 4; nj++) {
                int row = brow0 + nj * 16;
                uint32_t bd = sB + row * 128 + (((2 * ks + bkc) ^ (row & 7)) << 4);
                LDSM4(b[nj][0], b[nj][1], b[nj][2], b[nj][3], bd);
            }
#pragma unroll
            for (int mi = 0; mi < 4; mi++)
#pragma unroll
                for (int nj = 0; nj < 4; nj++) {
                    MMA16816(acc[mi][2 * nj],     a[mi][0], a[mi][1], a[mi][2], a[mi][3],
                             b[nj][0], b[nj][1]);
                    MMA16816(acc[mi][2 * nj + 1], a[mi][0], a[mi][1], a[mi][2], a[mi][3],
                             b[nj][2], b[nj][3]);
                }
        }
        if (++s == STAGES) s = 0;
    }

    const int mrow = bm * BM + wm * 64 + (lane >> 2);
    const int ncol = bn * BN + wn * 64 + 2 * (lane & 3);
#pragma unroll
    for (int nj = 0; nj < 8; nj++) {
        int c = ncol + nj * 8;
        float b0 = g_bias[c], b1 = g_bias[c + 1];
#pragma unroll
        for (int mi = 0; mi < 4; mi++) {
            int r0 = mrow + mi * 16;
            float2 v0 = make_float2(acc[mi][nj][0] + b0, acc[mi][nj][1] + b1);
            float2 v1 = make_float2(acc[mi][nj][2] + b0, acc[mi][nj][3] + b1);
            *(float2*)(C + (size_t)r0 * NCAT + c) = v0;
            *(float2*)(C + (size_t)(r0 + 8) * NCAT + c) = v1;
        }
    }
}

// ---------------- packed warp top-32-of-128 ---------------------------------
__device__ __forceinline__ uint32_t ordf(float f) {
    int b = __float_as_int(f);
    return (uint32_t)(b ^ ((b >> 31) | 0x80000000));
}
__device__ __forceinline__ float deordf(uint32_t u) {
    int b = (u & 0x80000000u) ? (int)(u ^ 0x80000000u) : ~(int)u;
    return __int_as_float(b);
}

#define PCEX(v, j, takeMax) do { \
    uint32_t _o = __shfl_xor_sync(0xffffffffu, (v), (j)); \
    (v) = (takeMax) ? ((v) > _o ? (v) : _o) : ((v) < _o ? (v) : _o); \
} while (0)

__device__ __forceinline__ uint32_t top32of128(uint32_t u[4], int lane)
{
#pragma unroll
    for (int k = 2; k <= 32; k <<= 1) {
#pragma unroll
        for (int j = k >> 1; j > 0; j >>= 1) {
            bool flag = (lane & k) == 0;
            bool lower = (lane & j) == 0;
            bool tm = (flag == lower);
#pragma unroll
            for (int r = 0; r < 4; r++) PCEX(u[r], j, tm);
        }
    }
    uint32_t a, b;
    {
        uint32_t o1 = __shfl_xor_sync(0xffffffffu, u[1], 31);
        uint32_t o3 = __shfl_xor_sync(0xffffffffu, u[3], 31);
        a = u[0] > o1 ? u[0] : o1;
        b = u[2] > o3 ? u[2] : o3;
    }
#pragma unroll
    for (int j = 16; j > 0; j >>= 1) {
        bool lower = (lane & j) == 0;
        PCEX(a, j, lower);
        PCEX(b, j, lower);
    }
    uint32_t m;
    {
        uint32_t ob = __shfl_xor_sync(0xffffffffu, b, 31);
        m = a > ob ? a : ob;
    }
#pragma unroll
    for (int j = 16; j > 0; j >>= 1) {
        bool lower = (lane & j) == 0;
        PCEX(m, j, lower);
    }
    return m;   // lane l = (l+1)-th largest
}

// ---------------- fused: top-k + softmax + gather + residual + LayerNorm ----
__global__ __launch_bounds__(192) void pkm_fused(
    const float* __restrict__ Cmat, const float* __restrict__ inp,
    const float* __restrict__ gamma, const float* __restrict__ beta,
    float* __restrict__ out)
{
    const int t = blockIdx.x;
    const int tid = threadIdx.x;
    const int wid = tid >> 5, lane = tid & 31;

    __shared__ float wsh[HEADS * KNN];
    __shared__ int   ish[HEADS * KNN];
    __shared__ float red[192];

    // ---- phase 1: per-head top-32 + softmax (warps 0-3) ----
    if (wid < HEADS) {
        const int h = wid;
        const float* Srow = Cmat + (size_t)t * NCAT + V_DIM + h * 256;

        uint32_t u[4];
#pragma unroll
        for (int r = 0; r < 4; r++) {
            int e = r * 32 + lane;
            u[r] = (ordf(Srow[e]) & 0xFFFFFF80u) | (uint32_t)e;
        }
        uint32_t top1 = top32of128(u, lane);
#pragma unroll
        for (int r = 0; r < 4; r++) {
            int e = r * 32 + lane;
            u[r] = (ordf(Srow[128 + e]) & 0xFFFFFF80u) | (uint32_t)e;
        }
        uint32_t top2 = top32of128(u, lane);

#pragma unroll
        for (int r = 0; r < 4; r++) {
            int c = r * 32 + lane;
            int tab = c_tab[c];
            int i = tab >> 5, jj = tab & 31;
            uint32_t k1 = __shfl_sync(0xffffffffu, top1, i);
            uint32_t k2 = __shfl_sync(0xffffffffu, top2, jj);
            float f = deordf(k1 & 0xFFFFFF80u) + deordf(k2 & 0xFFFFFF80u);
            u[r] = (c < 119) ? ((ordf(f) & 0xFFFFFF80u) | (uint32_t)c)
                             : (uint32_t)c;
        }
        uint32_t m = top32of128(u, lane);

        int c = m & 127;
        int tab = c_tab[c];
        int i = tab >> 5, jj = tab & 31;
        uint32_t k1 = __shfl_sync(0xffffffffu, top1, i);
        uint32_t k2 = __shfl_sync(0xffffffffu, top2, jj);
        int idx = (int)(k1 & 127u) * N_KEYS + (int)(k2 & 127u);
        float val = deordf(m & 0xFFFFFF80u);
        float mx = __shfl_sync(0xffffffffu, val, 0);
        float e = expf(val - mx);
        float sum = e;
#pragma unroll
        for (int o = 16; o > 0; o >>= 1) sum += __shfl_xor_sync(0xffffffffu, sum, o);
        wsh[h * KNN + lane] = e / sum;
        ish[h * KNN + lane] = idx;
    }
    __syncthreads();

    // ---- phase 2: gather + residual + LN (all 192 threads) ----
    float4 acc;
    {
        float4 d4 = ((const float4*)(Cmat + (size_t)t * NCAT))[tid];
        float4 r4 = ((const float4*)(inp  + (size_t)t * V_DIM))[tid];
        acc.x = d4.x + r4.x; acc.y = d4.y + r4.y;
        acc.z = d4.z + r4.z; acc.w = d4.w + r4.w;
    }

    float4 acc2 = make_float4(0.f, 0.f, 0.f, 0.f);
#pragma unroll 4
    for (int m = 0; m < HEADS * KNN; m += 2) {
        float w0 = wsh[m];
        ushort4 h0 = ((const ushort4*)(g_vb + (size_t)ish[m] * V_DIM))[tid];
        acc.x += w0 * __int_as_float((uint32_t)h0.x << 16);
        acc.y += w0 * __int_as_float((uint32_t)h0.y << 16);
        acc.z += w0 * __int_as_float((uint32_t)h0.z << 16);
        acc.w += w0 * __int_as_float((uint32_t)h0.w << 16);
        float w1 = wsh[m + 1];
        ushort4 h1 = ((const ushort4*)(g_vb + (size_t)ish[m + 1] * V_DIM))[tid];
        acc2.x += w1 * __int_as_float((uint32_t)h1.x << 16);
        acc2.y += w1 * __int_as_float((uint32_t)h1.y << 16);
        acc2.z += w1 * __int_as_float((uint32_t)h1.z << 16);
        acc2.w += w1 * __int_as_float((uint32_t)h1.w << 16);
    }
    acc.x += acc2.x; acc.y += acc2.y; acc.z += acc2.z; acc.w += acc2.w;

    red[tid] = acc.x + acc.y + acc.z + acc.w;
    __syncthreads();
    if (tid < 64) red[tid] += red[tid + 128];
    __syncthreads();
    if (tid < 64) red[tid] += red[tid + 64];
    __syncthreads();
    if (tid < 32) {
        float v = red[tid] + red[tid + 32];
#pragma unroll
        for (int o = 16; o > 0; o >>= 1) v += __shfl_xor_sync(0xffffffffu, v, o);
        if (tid == 0) red[0] = v;
    }
    __syncthreads();
    float mu = red[0] * (1.0f / V_DIM);
    __syncthreads();

    float dx = acc.x - mu, dy = acc.y - mu, dz = acc.z - mu, dw = acc.w - mu;
    red[tid] = dx * dx + dy * dy + dz * dz + dw * dw;
    __syncthreads();
    if (tid < 64) red[tid] += red[tid + 128];
    __syncthreads();
    if (tid < 64) red[tid] += red[tid + 64];
    __syncthreads();
    if (tid < 32) {
        float v = red[tid] + red[tid + 32];
#pragma unroll
        for (int o = 16; o > 0; o >>= 1) v += __shfl_xor_sync(0xffffffffu, v, o);
        if (tid == 0) red[0] = v;
    }
    __syncthreads();
    float var = red[0] * (1.0f / V_DIM);
    float rstd = rsqrtf(var + 1e-12f);

    float4 g4 = ((const float4*)gamma)[tid];
    float4 b4 = ((const float4*)beta)[tid];
    float4 o4;
    o4.x = dx * rstd * g4.x + b4.x;
    o4.y = dy * rstd * g4.y + b4.y;
    o4.z = dz * rstd * g4.z + b4.z;
    o4.w = dw * rstd * g4.w + b4.w;
    ((float4*)(out + (size_t)t * V_DIM))[tid] = o4;
}

// ---------------- launch ---------------------------------------------------
extern "C" void kernel_launch(void* const* d_in, const int* in_sizes, int n_in,
                              void* d_out, int out_size)
{
    const float* hs     = (const float*)d_in[0];
    const float* inp    = (const float*)d_in[1];
    const float* Wd     = (const float*)d_in[2];
    const float* bd     = (const float*)d_in[3];
    const float* Wq     = (const float*)d_in[4];
    const float* bq     = (const float*)d_in[5];
    const float* keys   = (const float*)d_in[6];
    const float* values = (const float*)d_in[7];
    const float* gamma  = (const float*)d_in[8];
    const float* beta   = (const float*)d_in[9];
    float* out = (float*)d_out;

    void* p_C;
    cudaGetSymbolAddress(&p_C, g_C);
    float* C = (float*)p_C;

    cudaFuncSetAttribute(gemm_hmma, cudaFuncAttributeMaxDynamicSharedMemorySize, SMEM_TOTAL);
    cudaFuncSetAttribute(prep_misc, cudaFuncAttributeMaxDynamicSharedMemorySize, PREP_SMEM);

    // one-time stream/event setup (host-side API only; no device memory)
    static cudaStream_t s_aux = nullptr;
    static cudaEvent_t evFork, evJoin;
    if (!s_aux) {
        cudaStreamCreateWithFlags(&s_aux, cudaStreamNonBlocking);
        cudaEventCreateWithFlags(&evFork, cudaEventDisableTiming);
        cudaEventCreateWithFlags(&evJoin, cudaEventDisableTiming);
    }

    // fork: DRAM-bound split_trans (default) || FMA-bound prep_misc + cvt (aux)
    cudaEventRecord(evFork, 0);
    cudaStreamWaitEvent(s_aux, evFork, 0);

    split_trans<<<49152 + 2304, 256>>>(hs, Wd);
    prep_misc<<<197, 256, PREP_SMEM, s_aux>>>(Wq, keys, bd, bq);
    cvt_values<<<(N_KEYS * N_KEYS * V_DIM / 4) / 256, 256, 0, s_aux>>>(values);

    // join before GEMM (gemm is the 4th launch = ncu capture slot)
    cudaEventRecord(evJoin, s_aux);
    cudaStreamWaitEvent(0, evJoin, 0);

    gemm_hmma<<<dim3(NCAT / BN, T_TOT / BM), 128, SMEM_TOTAL>>>(C);
    pkm_fused<<<T_TOT, 192>>>(C, inp, gamma, beta, out);
}

// round 17
// speedup vs baseline: 1.1863x; 1.0175x over previous
#include <cuda_runtime.h>
#include <cuda_fp16.h>
#include <cuda_bf16.h>
#include <math.h>
#include <float.h>
#include <stdint.h>

#define T_TOT   16384
#define IN_DIM  3072
#define V_DIM   768
#define HEADS   4
#define KNN     32
#define N_KEYS  128
#define NCAT    1792            // 768 (dense) + 1024 (scores)
#define BM      128
#define BN      128
#define BK      64
#define STAGES  3
#define NCHUNK  48              // IN_DIM / BK
#define STAGE_BYTES (BM * BK * 2 + BN * BK * 2)   // 32768
#define SMEM_TOTAL  (STAGES * STAGE_BYTES)        // 98304
#define PREP_SMEM   (128 * 132 * 4 + 128 * 128 * 4)  // 133120
#define VSCALE      16.0f

// ---------------- scratch (device globals; no allocation allowed) ----------
__device__ __align__(256) __half g_Ah[(size_t)T_TOT * IN_DIM];
__device__ __align__(256) __half g_Bh[(size_t)NCAT * IN_DIM];
__device__ __align__(256) float g_bias[NCAT];
__device__ __align__(256) float g_C[(size_t)T_TOT * NCAT];
__device__ __align__(256) unsigned char g_v8[(size_t)(N_KEYS * N_KEYS) * V_DIM];

// pruned product-key candidate table: (i<<5)|j for all (i+1)*(j+1) <= 32
__constant__ unsigned short c_tab[128] = {
    0,1,2,3,4,5,6,7,8,9,10,11,12,13,14,15,
    16,17,18,19,20,21,22,23,24,25,26,27,28,29,30,31,
    32,33,34,35,36,37,38,39,40,41,42,43,44,45,46,47,
    64,65,66,67,68,69,70,71,72,73,
    96,97,98,99,100,101,102,103,
    128,129,130,131,132,133,
    160,161,162,163,164,
    192,193,194,195,
    224,225,226,227,
    256,257,258,
    288,289,290,
    320,321, 352,353, 384,385, 416,417, 448,449, 480,481,
    512,544,576,608,640,672,704,736,768,800,832,864,896,928,960,992,
    0,0,0,0,0,0,0,0,0
};

// ---------------- PTX helpers ----------------------------------------------
__device__ __forceinline__ uint32_t smem_u32(const void* p) {
    uint32_t a;
    asm("{ .reg .u64 t; cvta.to.shared.u64 t, %1; cvt.u32.u64 %0, t; }" : "=r"(a) : "l"(p));
    return a;
}
#define SW128(off) ((off) ^ (((off) >> 3) & 0x70))

__device__ __forceinline__ void cp_async16(uint32_t dst, const void* src) {
    asm volatile("cp.async.cg.shared.global [%0], [%1], 16;" :: "r"(dst), "l"(src));
}
#define CP_COMMIT() asm volatile("cp.async.commit_group;" ::: "memory")
#define CP_WAIT1()  asm volatile("cp.async.wait_group 1;" ::: "memory")

#define LDSM4(r0, r1, r2, r3, addr) \
    asm volatile("ldmatrix.sync.aligned.m8n8.x4.shared.b16 {%0,%1,%2,%3}, [%4];" \
                 : "=r"(r0), "=r"(r1), "=r"(r2), "=r"(r3) : "r"(addr))

#define MMA16816(d, a0, a1, a2, a3, b0, b1) \
    asm volatile("mma.sync.aligned.m16n8k16.row.col.f32.f16.f16.f32 " \
                 "{%0,%1,%2,%3}, {%4,%5,%6,%7}, {%8,%9}, {%0,%1,%2,%3};" \
                 : "+f"((d)[0]), "+f"((d)[1]), "+f"((d)[2]), "+f"((d)[3]) \
                 : "r"(a0), "r"(a1), "r"(a2), "r"(a3), "r"(b0), "r"(b1))

// fp8 e4m3 pack/unpack (base ISA, sm_89+)
__device__ __forceinline__ unsigned short f32x2_to_e4m3x2(float lo, float hi) {
    unsigned short r;
    asm("cvt.rn.satfinite.e4m3x2.f32 %0, %1, %2;" : "=h"(r) : "f"(hi), "f"(lo));
    return r;
}
__device__ __forceinline__ float2 e4m3x2_to_f32x2(unsigned short u) {
    uint32_t h2;
    asm("cvt.rn.f16x2.e4m3x2 %0, %1;" : "=r"(h2) : "h"(u));
    __half2 hh = *reinterpret_cast<__half2*>(&h2);
    return __half22float2(hh);
}

// ---------------- prep: A -> fp16 + transpose W_dense -----------------------
__global__ __launch_bounds__(256) void split_trans(
    const float* __restrict__ X, const float* __restrict__ W)
{
    __shared__ float tile[32][33];
    const int b = blockIdx.x, t = threadIdx.x;
    if (b < 49152) {
        size_t i = (size_t)b * 256 + t;          // one float4
        float4 v = ((const float4*)X)[i];
        ushort4 h;
        h.x = __half_as_ushort(__float2half_rn(v.x));
        h.y = __half_as_ushort(__float2half_rn(v.y));
        h.z = __half_as_ushort(__float2half_rn(v.z));
        h.w = __half_as_ushort(__float2half_rn(v.w));
        ((ushort4*)g_Ah)[i] = h;
    } else {
        const int b2 = b - 49152;
        const int n0 = (b2 % 24) * 32, k0 = (b2 / 24) * 32;
        const int tx = t & 31, ty = t >> 5;
#pragma unroll
        for (int j = 0; j < 32; j += 8)
            tile[ty + j][tx] = W[(size_t)(k0 + ty + j) * V_DIM + n0 + tx];
        __syncthreads();
#pragma unroll
        for (int j = 0; j < 32; j += 8) {
            int n = n0 + ty + j, k = k0 + tx;
            g_Bh[(size_t)n * IN_DIM + k] = __float2half_rn(tile[tx][ty + j]);
        }
    }
}

// merged: W_keff = Wq x keys^T (rows 768..1791 of g_Bh), score bias, dense bias
// register-tiled: 64 accumulators/thread, float4 smem reads (FMA-bound)
__global__ __launch_bounds__(256) void prep_misc(
    const float* __restrict__ Wq, const float* __restrict__ keys,
    const float* __restrict__ bd, const float* __restrict__ bq)
{
    extern __shared__ float sm[];
    float (*Ws)[132] = (float(*)[132])sm;                 // [kloc][d] padded
    float (*Ks)[128] = (float(*)[128])(sm + 128 * 132);   // [n][d]
    const int b = blockIdx.x, t = threadIdx.x;

    if (b < 192) {
        const int hs = b & 7, kt = b >> 3;
        for (int i = t; i < 128 * 128; i += 256) {
            int r = i >> 7, d = i & 127;
            Ws[r][d] = Wq[(size_t)(kt * 128 + r) * 1024 + hs * 128 + d];
            Ks[r][d] = keys[(size_t)(hs * 128 + r) * 128 + d];
        }
        __syncthreads();
        const int kloc = t & 127, nh = t >> 7;
        float acc[64];
#pragma unroll
        for (int no = 0; no < 64; no++) acc[no] = 0.f;
        for (int d4 = 0; d4 < 128; d4 += 4) {
            float4 ws = *(const float4*)&Ws[kloc][d4];
#pragma unroll 16
            for (int no = 0; no < 64; no++) {
                float4 ks = *(const float4*)&Ks[nh * 64 + no][d4];
                acc[no] += ws.x * ks.x + ws.y * ks.y + ws.z * ks.z + ws.w * ks.w;
            }
        }
        for (int no = 0; no < 64; no++)
            g_Bh[(size_t)(V_DIM + hs * 128 + nh * 64 + no) * IN_DIM + kt * 128 + kloc] =
                __float2half_rn(acc[no]);
    } else if (b < 196) {
        int np = (b - 192) * 256 + t;     // 0..1023
        int hs = np >> 7, n = np & 127;
        float acc = 0.f;
        for (int d = 0; d < 128; d++)
            acc += bq[hs * 128 + d] * keys[(size_t)(hs * 128 + n) * 128 + d];
        g_bias[V_DIM + np] = acc;
    } else {
        for (int i = t; i < V_DIM; i += 256) g_bias[i] = bd[i];
    }
}

// ---------------- values table -> e4m3 (x VSCALE) ---------------------------
__global__ __launch_bounds__(256) void cvt_values(const float* __restrict__ v)
{
    size_t i = (size_t)blockIdx.x * 256 + threadIdx.x;   // one float4 -> 4 bytes
    float4 x = ((const float4*)v)[i];
    unsigned short a = f32x2_to_e4m3x2(x.x * VSCALE, x.y * VSCALE);
    unsigned short b = f32x2_to_e4m3x2(x.z * VSCALE, x.w * VSCALE);
    ((uint32_t*)g_v8)[i] = (uint32_t)a | ((uint32_t)b << 16);
}

// ---------------- HMMA GEMM: 128x128 CTA tile, 64x64 warp tile, 2 CTA/SM ---
__device__ __forceinline__ void load_chunk(
    int chunk, int s, int tid, int bm, int bn, uint32_t sb)
{
    int k0 = chunk * BK;
    const __half* Ag = g_Ah + (size_t)(bm * BM) * IN_DIM + k0;
    const __half* Bg = g_Bh + (size_t)(bn * BN) * IN_DIM + k0;
    uint32_t sA = sb + s * STAGE_BYTES;
    uint32_t sB = sA + BM * BK * 2;
#pragma unroll
    for (int it = 0; it < 8; it++) {      // A: 1024 x 16B over 128 threads
        int u = tid + it * 128;
        int r = u >> 3, ch = u & 7;
        cp_async16(sA + SW128(r * 128 + ch * 16), Ag + (size_t)r * IN_DIM + ch * 8);
    }
#pragma unroll
    for (int it = 0; it < 8; it++) {      // B: 1024 x 16B
        int u = tid + it * 128;
        int r = u >> 3, ch = u & 7;
        cp_async16(sB + SW128(r * 128 + ch * 16), Bg + (size_t)r * IN_DIM + ch * 8);
    }
}

__global__ __launch_bounds__(128, 2) void gemm_hmma(float* __restrict__ C)
{
    extern __shared__ char smem[];
    uint32_t sb = smem_u32(smem);
    const int tid = threadIdx.x, wid = tid >> 5, lane = tid & 31;
    const int bn = blockIdx.x, bm = blockIdx.y;
    const int wm = wid & 1;          // M half: rows wm*64
    const int wn = wid >> 1;         // N half: cols wn*64

    float acc[4][8][4];
#pragma unroll
    for (int a = 0; a < 4; a++)
#pragma unroll
        for (int b = 0; b < 8; b++)
#pragma unroll
            for (int c = 0; c < 4; c++) acc[a][b][c] = 0.f;

    const int sub = lane >> 3, lr = lane & 7;
    const int arow0 = wm * 64 + ((sub & 1) << 3) + lr;   // + mi*16
    const int akc = sub >> 1;
    const int brow0 = wn * 64 + ((sub >> 1) << 3) + lr;  // + nj*16
    const int bkc = sub & 1;

#pragma unroll
    for (int s = 0; s < STAGES - 1; s++) {
        load_chunk(s, s, tid, bm, bn, sb);
        CP_COMMIT();
    }

    int s = 0;
    for (int i = 0; i < NCHUNK; i++) {
        CP_WAIT1();
        __syncthreads();
        const int nc = i + STAGES - 1;
        if (nc < NCHUNK) {
            int sp = s + STAGES - 1; if (sp >= STAGES) sp -= STAGES;
            load_chunk(nc, sp, tid, bm, bn, sb);
        }
        CP_COMMIT();

        const uint32_t sA = sb + s * STAGE_BYTES;
        const uint32_t sB = sA + BM * BK * 2;
#pragma unroll
        for (int ks = 0; ks < 4; ks++) {
            uint32_t a[4][4];
#pragma unroll
            for (int mi = 0; mi < 4; mi++) {
                int row = arow0 + mi * 16;
                uint32_t ad = sA + row * 128 + (((2 * ks + akc) ^ (row & 7)) << 4);
                LDSM4(a[mi][0], a[mi][1], a[mi][2], a[mi][3], ad);
            }
            uint32_t b[4][4];
#pragma unroll
            for (int nj = 0; nj < 4; nj++) {
                int row = brow0 + nj * 16;
                uint32_t bd = sB + row * 128 + (((2 * ks + bkc) ^ (row & 7)) << 4);
                LDSM4(b[nj][0], b[nj][1], b[nj][2], b[nj][3], bd);
            }
#pragma unroll
            for (int mi = 0; mi < 4; mi++)
#pragma unroll
                for (int nj = 0; nj < 4; nj++) {
                    MMA16816(acc[mi][2 * nj],     a[mi][0], a[mi][1], a[mi][2], a[mi][3],
                             b[nj][0], b[nj][1]);
                    MMA16816(acc[mi][2 * nj + 1], a[mi][0], a[mi][1], a[mi][2], a[mi][3],
                             b[nj][2], b[nj][3]);
                }
        }
        if (++s == STAGES) s = 0;
    }

    const int mrow = bm * BM + wm * 64 + (lane >> 2);
    const int ncol = bn * BN + wn * 64 + 2 * (lane & 3);
#pragma unroll
    for (int nj = 0; nj < 8; nj++) {
        int c = ncol + nj * 8;
        float b0 = g_bias[c], b1 = g_bias[c + 1];
#pragma unroll
        for (int mi = 0; mi < 4; mi++) {
            int r0 = mrow + mi * 16;
            float2 v0 = make_float2(acc[mi][nj][0] + b0, acc[mi][nj][1] + b1);
            float2 v1 = make_float2(acc[mi][nj][2] + b0, acc[mi][nj][3] + b1);
            *(float2*)(C + (size_t)r0 * NCAT + c) = v0;
            *(float2*)(C + (size_t)(r0 + 8) * NCAT + c) = v1;
        }
    }
}

// ---------------- packed warp top-32-of-128 ---------------------------------
__device__ __forceinline__ uint32_t ordf(float f) {
    int b = __float_as_int(f);
    return (uint32_t)(b ^ ((b >> 31) | 0x80000000));
}
__device__ __forceinline__ float deordf(uint32_t u) {
    int b = (u & 0x80000000u) ? (int)(u ^ 0x80000000u) : ~(int)u;
    return __int_as_float(b);
}

#define PCEX(v, j, takeMax) do { \
    uint32_t _o = __shfl_xor_sync(0xffffffffu, (v), (j)); \
    (v) = (takeMax) ? ((v) > _o ? (v) : _o) : ((v) < _o ? (v) : _o); \
} while (0)

__device__ __forceinline__ uint32_t top32of128(uint32_t u[4], int lane)
{
#pragma unroll
    for (int k = 2; k <= 32; k <<= 1) {
#pragma unroll
        for (int j = k >> 1; j > 0; j >>= 1) {
            bool flag = (lane & k) == 0;
            bool lower = (lane & j) == 0;
            bool tm = (flag == lower);
#pragma unroll
            for (int r = 0; r < 4; r++) PCEX(u[r], j, tm);
        }
    }
    uint32_t a, b;
    {
        uint32_t o1 = __shfl_xor_sync(0xffffffffu, u[1], 31);
        uint32_t o3 = __shfl_xor_sync(0xffffffffu, u[3], 31);
        a = u[0] > o1 ? u[0] : o1;
        b = u[2] > o3 ? u[2] : o3;
    }
#pragma unroll
    for (int j = 16; j > 0; j >>= 1) {
        bool lower = (lane & j) == 0;
        PCEX(a, j, lower);
        PCEX(b, j, lower);
    }
    uint32_t m;
    {
        uint32_t ob = __shfl_xor_sync(0xffffffffu, b, 31);
        m = a > ob ? a : ob;
    }
#pragma unroll
    for (int j = 16; j > 0; j >>= 1) {
        bool lower = (lane & j) == 0;
        PCEX(m, j, lower);
    }
    return m;   // lane l = (l+1)-th largest
}

// ---------------- fused: top-k + softmax + gather + residual + LayerNorm ----
__global__ __launch_bounds__(192) void pkm_fused(
    const float* __restrict__ Cmat, const float* __restrict__ inp,
    const float* __restrict__ gamma, const float* __restrict__ beta,
    float* __restrict__ out)
{
    const int t = blockIdx.x;
    const int tid = threadIdx.x;
    const int wid = tid >> 5, lane = tid & 31;

    __shared__ float wsh[HEADS * KNN];
    __shared__ int   ish[HEADS * KNN];
    __shared__ float red[192];

    // ---- phase 1: per-head top-32 + softmax (warps 0-3) ----
    if (wid < HEADS) {
        const int h = wid;
        const float* Srow = Cmat + (size_t)t * NCAT + V_DIM + h * 256;

        uint32_t u[4];
#pragma unroll
        for (int r = 0; r < 4; r++) {
            int e = r * 32 + lane;
            u[r] = (ordf(Srow[e]) & 0xFFFFFF80u) | (uint32_t)e;
        }
        uint32_t top1 = top32of128(u, lane);
#pragma unroll
        for (int r = 0; r < 4; r++) {
            int e = r * 32 + lane;
            u[r] = (ordf(Srow[128 + e]) & 0xFFFFFF80u) | (uint32_t)e;
        }
        uint32_t top2 = top32of128(u, lane);

#pragma unroll
        for (int r = 0; r < 4; r++) {
            int c = r * 32 + lane;
            int tab = c_tab[c];
            int i = tab >> 5, jj = tab & 31;
            uint32_t k1 = __shfl_sync(0xffffffffu, top1, i);
            uint32_t k2 = __shfl_sync(0xffffffffu, top2, jj);
            float f = deordf(k1 & 0xFFFFFF80u) + deordf(k2 & 0xFFFFFF80u);
            u[r] = (c < 119) ? ((ordf(f) & 0xFFFFFF80u) | (uint32_t)c)
                             : (uint32_t)c;
        }
        uint32_t m = top32of128(u, lane);

        int c = m & 127;
        int tab = c_tab[c];
        int i = tab >> 5, jj = tab & 31;
        uint32_t k1 = __shfl_sync(0xffffffffu, top1, i);
        uint32_t k2 = __shfl_sync(0xffffffffu, top2, jj);
        int idx = (int)(k1 & 127u) * N_KEYS + (int)(k2 & 127u);
        float val = deordf(m & 0xFFFFFF80u);
        float mx = __shfl_sync(0xffffffffu, val, 0);
        float e = expf(val - mx);
        float sum = e;
#pragma unroll
        for (int o = 16; o > 0; o >>= 1) sum += __shfl_xor_sync(0xffffffffu, sum, o);
        wsh[h * KNN + lane] = e / (sum * VSCALE);   // fold 1/VSCALE into weight
        ish[h * KNN + lane] = idx;
    }
    __syncthreads();

    // ---- phase 2: gather (e4m3) + residual + LN (all 192 threads) ----
    float4 acc;
    {
        float4 d4 = ((const float4*)(Cmat + (size_t)t * NCAT))[tid];
        float4 r4 = ((const float4*)(inp  + (size_t)t * V_DIM))[tid];
        acc.x = d4.x + r4.x; acc.y = d4.y + r4.y;
        acc.z = d4.z + r4.z; acc.w = d4.w + r4.w;
    }

    float4 acc2 = make_float4(0.f, 0.f, 0.f, 0.f);
#pragma unroll 4
    for (int m = 0; m < HEADS * KNN; m += 2) {
        float w0 = wsh[m];
        uint32_t p0 = ((const uint32_t*)(g_v8 + (size_t)ish[m] * V_DIM))[tid];
        float2 a0 = e4m3x2_to_f32x2((unsigned short)(p0 & 0xFFFF));
        float2 b0 = e4m3x2_to_f32x2((unsigned short)(p0 >> 16));
        acc.x += w0 * a0.x; acc.y += w0 * a0.y;
        acc.z += w0 * b0.x; acc.w += w0 * b0.y;
        float w1 = wsh[m + 1];
        uint32_t p1 = ((const uint32_t*)(g_v8 + (size_t)ish[m + 1] * V_DIM))[tid];
        float2 a1 = e4m3x2_to_f32x2((unsigned short)(p1 & 0xFFFF));
        float2 b1 = e4m3x2_to_f32x2((unsigned short)(p1 >> 16));
        acc2.x += w1 * a1.x; acc2.y += w1 * a1.y;
        acc2.z += w1 * b1.x; acc2.w += w1 * b1.y;
    }
    acc.x += acc2.x; acc.y += acc2.y; acc.z += acc2.z; acc.w += acc2.w;

    red[tid] = acc.x + acc.y + acc.z + acc.w;
    __syncthreads();
    if (tid < 64) red[tid] += red[tid + 128];
    __syncthreads();
    if (tid < 64) red[tid] += red[tid + 64];
    __syncthreads();
    if (tid < 32) {
        float v = red[tid] + red[tid + 32];
#pragma unroll
        for (int o = 16; o > 0; o >>= 1) v += __shfl_xor_sync(0xffffffffu, v, o);
        if (tid == 0) red[0] = v;
    }
    __syncthreads();
    float mu = red[0] * (1.0f / V_DIM);
    __syncthreads();

    float dx = acc.x - mu, dy = acc.y - mu, dz = acc.z - mu, dw = acc.w - mu;
    red[tid] = dx * dx + dy * dy + dz * dz + dw * dw;
    __syncthreads();
    if (tid < 64) red[tid] += red[tid + 128];
    __syncthreads();
    if (tid < 64) red[tid] += red[tid + 64];
    __syncthreads();
    if (tid < 32) {
        float v = red[tid] + red[tid + 32];
#pragma unroll
        for (int o = 16; o > 0; o >>= 1) v += __shfl_xor_sync(0xffffffffu, v, o);
        if (tid == 0) red[0] = v;
    }
    __syncthreads();
    float var = red[0] * (1.0f / V_DIM);
    float rstd = rsqrtf(var + 1e-12f);

    float4 g4 = ((const float4*)gamma)[tid];
    float4 b4 = ((const float4*)beta)[tid];
    float4 o4;
    o4.x = dx * rstd * g4.x + b4.x;
    o4.y = dy * rstd * g4.y + b4.y;
    o4.z = dz * rstd * g4.z + b4.z;
    o4.w = dw * rstd * g4.w + b4.w;
    ((float4*)(out + (size_t)t * V_DIM))[tid] = o4;
}

// ---------------- launch ---------------------------------------------------
extern "C" void kernel_launch(void* const* d_in, const int* in_sizes, int n_in,
                              void* d_out, int out_size)
{
    const float* hs     = (const float*)d_in[0];
    const float* inp    = (const float*)d_in[1];
    const float* Wd     = (const float*)d_in[2];
    const float* bd     = (const float*)d_in[3];
    const float* Wq     = (const float*)d_in[4];
    const float* bq     = (const float*)d_in[5];
    const float* keys   = (const float*)d_in[6];
    const float* values = (const float*)d_in[7];
    const float* gamma  = (const float*)d_in[8];
    const float* beta   = (const float*)d_in[9];
    float* out = (float*)d_out;

    void* p_C;
    cudaGetSymbolAddress(&p_C, g_C);
    float* C = (float*)p_C;

    cudaFuncSetAttribute(gemm_hmma, cudaFuncAttributeMaxDynamicSharedMemorySize, SMEM_TOTAL);
    cudaFuncSetAttribute(prep_misc, cudaFuncAttributeMaxDynamicSharedMemorySize, PREP_SMEM);

    // one-time stream/event setup (host-side API only; no device memory)
    static cudaStream_t s_aux = nullptr;
    static cudaEvent_t evFork, evJoin;
    if (!s_aux) {
        cudaStreamCreateWithFlags(&s_aux, cudaStreamNonBlocking);
        cudaEventCreateWithFlags(&evFork, cudaEventDisableTiming);
        cudaEventCreateWithFlags(&evJoin, cudaEventDisableTiming);
    }

    // fork: DRAM-bound split_trans (default) || FMA-bound prep_misc + cvt (aux)
    cudaEventRecord(evFork, 0);
    cudaStreamWaitEvent(s_aux, evFork, 0);

    split_trans<<<49152 + 2304, 256>>>(hs, Wd);
    prep_misc<<<197, 256, PREP_SMEM, s_aux>>>(Wq, keys, bd, bq);
    cvt_values<<<(N_KEYS * N_KEYS * V_DIM / 4) / 256, 256, 0, s_aux>>>(values);

    // join before GEMM (gemm is the 4th launch = ncu capture slot)
    cudaEventRecord(evJoin, s_aux);
    cudaStreamWaitEvent(0, evJoin, 0);

    gemm_hmma<<<dim3(NCAT / BN, T_TOT / BM), 128, SMEM_TOTAL>>>(C);
    pkm_fused<<<T_TOT, 192>>>(C, inp, gamma, beta, out);
}